// round 1
// baseline (speedup 1.0000x reference)
#include <cuda_runtime.h>
#include <math.h>

#define N_NODES 50000
#define NE      800000
#define ETOT    850000   /* NE + N_NODES (self loops) */
#define DIN     384
#define HID     256
#define HEADS   4
#define CDIM    64
#define EDIM    32
#define NLAYER  2
#define SLOPE   0.2f
#define TOT_H   (N_NODES*HID)   /* 12,800,000 ; divisible by 256 */

// ---------------- scratch (static device globals; no allocation) -------------
__device__ float    g_h [(size_t)N_NODES*HID];
__device__ float    g_xl[(size_t)N_NODES*HID];
__device__ float    g_xr[(size_t)N_NODES*HID];
__device__ float    g_ep[(size_t)ETOT*HID];          // 870 MB
__device__ float    g_loopea[(size_t)N_NODES*EDIM];
__device__ float    g_deg[N_NODES];
__device__ float    g_logits[(size_t)ETOT*HEADS];
__device__ unsigned g_lmax[N_NODES*HEADS];
__device__ float    g_denom[N_NODES*HEADS];
__device__ float    g_hn[(size_t)N_NODES*HID];
__device__ double   g_red[2];

// ---------------- helpers ----------------------------------------------------
__device__ __forceinline__ unsigned encf(float f){
    unsigned u = __float_as_uint(f);
    return (u & 0x80000000u) ? ~u : (u | 0x80000000u);
}
__device__ __forceinline__ float decf(unsigned e){
    return (e & 0x80000000u) ? __uint_as_float(e ^ 0x80000000u)
                             : __uint_as_float(~e);
}
__device__ __forceinline__ float lrelu(float x){ return x > 0.f ? x : SLOPE*x; }

// ---------------- zero kernels ----------------------------------------------
__global__ void k_zero_f(float* p, size_t n){
    size_t i = (size_t)blockIdx.x*blockDim.x + threadIdx.x;
    if (i < n) p[i] = 0.f;
}
__global__ void k_zero_u(unsigned* p, size_t n){
    size_t i = (size_t)blockIdx.x*blockDim.x + threadIdx.x;
    if (i < n) p[i] = 0u;
}
__global__ void k_zero_red(){ if (threadIdx.x < 2) g_red[threadIdx.x] = 0.0; }

// ---------------- degree + self-loop edge attr -------------------------------
__global__ void k_degree(const int* __restrict__ dst, const float* __restrict__ ea){
    int t = blockIdx.x*blockDim.x + threadIdx.x;
    if (t >= NE*8) return;
    int e = t >> 3, q = t & 7;
    int d = dst[e];
    float4 v = *(const float4*)(ea + (size_t)e*EDIM + q*4);
    float* base = g_loopea + (size_t)d*EDIM + q*4;
    atomicAdd(base+0, v.x); atomicAdd(base+1, v.y);
    atomicAdd(base+2, v.z); atomicAdd(base+3, v.w);
    if (q == 0) atomicAdd(&g_deg[d], 1.f);
}
__global__ void k_divloop(){
    int t = blockIdx.x*blockDim.x + threadIdx.x;
    if (t >= N_NODES*EDIM) return;
    float d = g_deg[t >> 5];       // EDIM = 32
    g_loopea[t] = g_loopea[t] / fmaxf(d, 1.f);
}

// ---------------- generic fp32 SGEMM: C = act(A @ B + bias) ------------------
// A is MxK row-major (rows >= splitRow come from A2), B KxN row-major.
// BM=BN=128, BK=8, 256 threads, 8x8 per thread. N must be multiple of 128,
// K multiple of 8. act: 0 none, 1 relu.
__global__ __launch_bounds__(256) void sgemm(
    const float* __restrict__ A, const float* __restrict__ A2, int splitRow,
    const float* __restrict__ B, const float* __restrict__ bias,
    float* __restrict__ C, int M, int K, int Nn, int act)
{
    __shared__ float As[8][128];
    __shared__ float Bs[8][128];
    const int cRow = blockIdx.y * 128;
    const int cCol = blockIdx.x * 128;
    const int tid  = threadIdx.x;
    const int rowA = tid >> 1,  colA = (tid & 1) * 4;
    const int rowB = tid >> 5,  colB = (tid & 31) * 4;
    const int tr = (tid >> 4) * 8;
    const int tc = (tid & 15) * 8;
    float acc[8][8];
    #pragma unroll
    for (int i = 0; i < 8; i++)
        #pragma unroll
        for (int j = 0; j < 8; j++) acc[i][j] = 0.f;

    for (int kt = 0; kt < K; kt += 8) {
        int gr = cRow + rowA;
        float4 av = make_float4(0.f,0.f,0.f,0.f);
        if (gr < M) {
            const float* Ab = (gr < splitRow) ? (A + (size_t)gr*K)
                                              : (A2 + (size_t)(gr - splitRow)*K);
            av = *(const float4*)(Ab + kt + colA);
        }
        As[colA+0][rowA] = av.x; As[colA+1][rowA] = av.y;
        As[colA+2][rowA] = av.z; As[colA+3][rowA] = av.w;
        float4 bv = *(const float4*)(B + (size_t)(kt + rowB)*Nn + cCol + colB);
        *(float4*)(&Bs[rowB][colB]) = bv;
        __syncthreads();
        #pragma unroll
        for (int k = 0; k < 8; k++) {
            float4 a0 = *(const float4*)&As[k][tr];
            float4 a1 = *(const float4*)&As[k][tr+4];
            float4 b0 = *(const float4*)&Bs[k][tc];
            float4 b1 = *(const float4*)&Bs[k][tc+4];
            float ra[8] = {a0.x,a0.y,a0.z,a0.w,a1.x,a1.y,a1.z,a1.w};
            float rb[8] = {b0.x,b0.y,b0.z,b0.w,b1.x,b1.y,b1.z,b1.w};
            #pragma unroll
            for (int i = 0; i < 8; i++)
                #pragma unroll
                for (int j = 0; j < 8; j++) acc[i][j] += ra[i]*rb[j];
        }
        __syncthreads();
    }
    #pragma unroll
    for (int i = 0; i < 8; i++) {
        int r = cRow + tr + i;
        if (r >= M) continue;
        #pragma unroll
        for (int j = 0; j < 8; j += 4) {
            int col = cCol + tc + j;
            float4 v = make_float4(acc[i][j], acc[i][j+1], acc[i][j+2], acc[i][j+3]);
            if (bias) {
                v.x += bias[col];   v.y += bias[col+1];
                v.z += bias[col+2]; v.w += bias[col+3];
            }
            if (act == 1) {
                v.x = fmaxf(v.x, 0.f); v.y = fmaxf(v.y, 0.f);
                v.z = fmaxf(v.z, 0.f); v.w = fmaxf(v.w, 0.f);
            }
            *(float4*)(C + (size_t)r*Nn + col) = v;
        }
    }
}

// ---------------- edge: logits + segment max ---------------------------------
__global__ __launch_bounds__(256) void k_logits(const int* __restrict__ src,
                                                const int* __restrict__ dst,
                                                const float* __restrict__ att)
{
    int gw   = (int)((blockIdx.x*(unsigned)blockDim.x + threadIdx.x) >> 5);
    int lane = threadIdx.x & 31;
    if (gw >= ETOT) return;
    int s, d;
    if (gw < NE) { s = src[gw]; d = dst[gw]; } else { s = gw - NE; d = s; }
    const float4* pl = (const float4*)(g_xl + (size_t)s*HID) + lane*2;
    const float4* pr = (const float4*)(g_xr + (size_t)d*HID) + lane*2;
    const float4* pe = (const float4*)(g_ep + (size_t)gw*HID) + lane*2;
    int head = lane >> 3;
    const float4* pa = (const float4*)(att + head*CDIM + (lane & 7)*8);
    float acc = 0.f;
    #pragma unroll
    for (int j = 0; j < 2; j++) {
        float4 a = pl[j], b = pr[j], c = pe[j], w = pa[j];
        acc += lrelu(a.x+b.x+c.x)*w.x;
        acc += lrelu(a.y+b.y+c.y)*w.y;
        acc += lrelu(a.z+b.z+c.z)*w.z;
        acc += lrelu(a.w+b.w+c.w)*w.w;
    }
    acc += __shfl_down_sync(0xffffffffu, acc, 4, 8);
    acc += __shfl_down_sync(0xffffffffu, acc, 2, 8);
    acc += __shfl_down_sync(0xffffffffu, acc, 1, 8);
    if ((lane & 7) == 0) {
        g_logits[(size_t)gw*HEADS + head] = acc;
        atomicMax(&g_lmax[d*HEADS + head], encf(acc));
    }
}

// ---------------- edge: exp + segment sum ------------------------------------
__global__ void k_expsum(const int* __restrict__ dst){
    int t = blockIdx.x*blockDim.x + threadIdx.x;
    if (t >= ETOT*HEADS) return;
    int e = t >> 2, hh = t & 3;
    int d = (e < NE) ? dst[e] : (e - NE);
    float ex = expf(g_logits[t] - decf(g_lmax[d*HEADS + hh]));
    g_logits[t] = ex;
    atomicAdd(&g_denom[d*HEADS + hh], ex);
}

// ---------------- edge: weighted aggregation ---------------------------------
__global__ __launch_bounds__(256) void k_agg(const int* __restrict__ src,
                                             const int* __restrict__ dst)
{
    int gw   = (int)((blockIdx.x*(unsigned)blockDim.x + threadIdx.x) >> 5);
    int lane = threadIdx.x & 31;
    if (gw >= ETOT) return;
    int s, d;
    if (gw < NE) { s = src[gw]; d = dst[gw]; } else { s = gw - NE; d = s; }
    int head = lane >> 3;
    float ex = g_logits[(size_t)gw*HEADS + head];
    float dn = g_denom[d*HEADS + head];
    float w  = ex / (dn + 1e-16f);
    const float4* pl = (const float4*)(g_xl + (size_t)s*HID) + lane*2;
    float* po = g_hn + (size_t)d*HID + lane*8;
    #pragma unroll
    for (int j = 0; j < 2; j++) {
        float4 a = pl[j];
        atomicAdd(po + j*4 + 0, w*a.x);
        atomicAdd(po + j*4 + 1, w*a.y);
        atomicAdd(po + j*4 + 2, w*a.z);
        atomicAdd(po + j*4 + 3, w*a.w);
    }
}

// ---------------- elu + residual + global sum/sumsq --------------------------
__global__ __launch_bounds__(256) void k_post(const float* __restrict__ bconv){
    int idx = blockIdx.x*blockDim.x + threadIdx.x;   // grid is exact (TOT_H/256)
    int c = idx & (HID-1);
    float v  = g_hn[idx] + bconv[c];
    float el = v > 0.f ? v : (expf(v) - 1.f);
    float t  = g_h[idx] + el;
    g_h[idx] = t;
    float s = t, q = t*t;
    #pragma unroll
    for (int off = 16; off; off >>= 1) {
        s += __shfl_down_sync(0xffffffffu, s, off);
        q += __shfl_down_sync(0xffffffffu, q, off);
    }
    __shared__ float ss[8], sq[8];
    int lane = threadIdx.x & 31, w = threadIdx.x >> 5;
    if (lane == 0) { ss[w] = s; sq[w] = q; }
    __syncthreads();
    if (threadIdx.x == 0) {
        float S = 0.f, Q = 0.f;
        #pragma unroll
        for (int i = 0; i < 8; i++) { S += ss[i]; Q += sq[i]; }
        atomicAdd(&g_red[0], (double)S);
        atomicAdd(&g_red[1], (double)Q);
    }
}

// ---------------- graph layer norm apply -------------------------------------
__global__ void k_norm(const float* __restrict__ lnw, const float* __restrict__ lnb){
    int idx = blockIdx.x*blockDim.x + threadIdx.x;
    if (idx >= TOT_H) return;
    int c = idx & (HID-1);
    double M  = (double)TOT_H;
    double mu = g_red[0] / M;
    double var = g_red[1] / M - mu*mu;
    if (var < 0.0) var = 0.0;
    float rs = (float)(1.0 / (sqrt(var) + 1e-5));
    g_h[idx] = (g_h[idx] - (float)mu) * rs * lnw[c] + lnb[c];
}

// ---------------- launcher ---------------------------------------------------
extern "C" void kernel_launch(void* const* d_in, const int* in_sizes, int n_in,
                              void* d_out, int out_size)
{
    const float* x     = (const float*)d_in[0];
    const int*   ei    = (const int*)  d_in[1];
    const float* ea    = (const float*)d_in[2];
    const float* w_in  = (const float*)d_in[3];
    const float* b_in  = (const float*)d_in[4];
    const float* wl    = (const float*)d_in[5];
    const float* wr    = (const float*)d_in[6];
    const float* we    = (const float*)d_in[7];
    const float* att   = (const float*)d_in[8];
    const float* bconv = (const float*)d_in[9];
    const float* lnw   = (const float*)d_in[10];
    const float* lnb   = (const float*)d_in[11];
    const float* wout  = (const float*)d_in[12];
    const float* bout  = (const float*)d_in[13];
    float* out = (float*)d_out;
    const int* srcA = ei;
    const int* dstA = ei + NE;

    float *p_h, *p_xl, *p_xr, *p_ep, *p_loop, *p_deg, *p_log, *p_den, *p_hn;
    unsigned* p_lm;
    cudaGetSymbolAddress((void**)&p_h,   g_h);
    cudaGetSymbolAddress((void**)&p_xl,  g_xl);
    cudaGetSymbolAddress((void**)&p_xr,  g_xr);
    cudaGetSymbolAddress((void**)&p_ep,  g_ep);
    cudaGetSymbolAddress((void**)&p_loop,g_loopea);
    cudaGetSymbolAddress((void**)&p_deg, g_deg);
    cudaGetSymbolAddress((void**)&p_log, g_logits);
    cudaGetSymbolAddress((void**)&p_den, g_denom);
    cudaGetSymbolAddress((void**)&p_hn,  g_hn);
    cudaGetSymbolAddress((void**)&p_lm,  g_lmax);

    // self-loop edge attributes
    k_zero_f<<<(unsigned)(((size_t)N_NODES*EDIM + 511)/512), 512>>>(p_loop, (size_t)N_NODES*EDIM);
    k_zero_f<<<(N_NODES + 511)/512, 512>>>(p_deg, (size_t)N_NODES);
    k_degree<<<(NE*8 + 255)/256, 256>>>(dstA, ea);
    k_divloop<<<(N_NODES*EDIM + 255)/256, 256>>>();

    // input projection
    dim3 gN(HID/128, (N_NODES + 127)/128);
    dim3 gE(HID/128, (ETOT + 127)/128);
    sgemm<<<gN, 256>>>(x, nullptr, N_NODES, w_in, b_in, p_h, N_NODES, DIN, HID, 1);

    for (int l = 0; l < NLAYER; l++) {
        sgemm<<<gN, 256>>>(p_h, nullptr, N_NODES, wl + (size_t)l*HID*HID, nullptr,
                           p_xl, N_NODES, HID, HID, 0);
        sgemm<<<gN, 256>>>(p_h, nullptr, N_NODES, wr + (size_t)l*HID*HID, nullptr,
                           p_xr, N_NODES, HID, HID, 0);
        sgemm<<<gE, 256>>>(ea, p_loop, NE, we + (size_t)l*EDIM*HID, nullptr,
                           p_ep, ETOT, EDIM, HID, 0);

        k_zero_u<<<(N_NODES*HEADS + 511)/512, 512>>>(p_lm, (size_t)N_NODES*HEADS);
        k_zero_f<<<(N_NODES*HEADS + 511)/512, 512>>>(p_den, (size_t)N_NODES*HEADS);
        k_zero_f<<<(unsigned)(((size_t)TOT_H + 511)/512), 512>>>(p_hn, (size_t)TOT_H);
        k_zero_red<<<1, 32>>>();

        k_logits<<<(ETOT + 7)/8, 256>>>(srcA, dstA, att + (size_t)l*HEADS*CDIM);
        k_expsum<<<(ETOT*HEADS + 255)/256, 256>>>(dstA);
        k_agg<<<(ETOT + 7)/8, 256>>>(srcA, dstA);
        k_post<<<TOT_H/256, 256>>>(bconv + (size_t)l*HID);
        k_norm<<<TOT_H/256, 256>>>(lnw + (size_t)l*HID, lnb + (size_t)l*HID);
    }

    sgemm<<<gN, 256>>>(p_h, nullptr, N_NODES, wout, bout, out, N_NODES, HID, HID, 0);
}

// round 3
// speedup vs baseline: 1.6184x; 1.6184x over previous
#include <cuda_runtime.h>
#include <math.h>

#define N_NODES 50000
#define NE      800000
#define ETOT    850000   /* NE + N_NODES self loops */
#define DIN     384
#define HID     256
#define HEADS   4
#define CDIM    64
#define EDIM    32
#define NLAYER  2
#define SLOPE   0.2f
#define TOT_H   (N_NODES*HID)

// ---------------- scratch (static device globals) ----------------------------
__device__ float    g_h   [(size_t)N_NODES*HID];
__device__ float    g_xlr [(size_t)N_NODES*512];     // [n][0:256]=xl, [256:512]=xr
__device__ float    g_loopea[(size_t)N_NODES*EDIM];
__device__ float    g_deg [N_NODES];
__device__ float    g_logits[(size_t)ETOT*HEADS];
__device__ int      g_csr_ptr[N_NODES+1];
__device__ int      g_cursor [N_NODES];
__device__ int      g_csr_e [ETOT];
__device__ int      g_csr_s [ETOT];
__device__ float    g_wcat[(size_t)HID*512];
__device__ double   g_red[2];

// ---------------- helpers ----------------------------------------------------
__device__ __forceinline__ float lrelu(float x){ return x > 0.f ? x : SLOPE*x; }
__device__ __forceinline__ float sel4(float4 v, int h){
    return h==0 ? v.x : (h==1 ? v.y : (h==2 ? v.z : v.w));
}

// ---------------- zero / setup ----------------------------------------------
__global__ void k_zero_f(float* p, size_t n){
    size_t i = (size_t)blockIdx.x*blockDim.x + threadIdx.x;
    if (i < n) p[i] = 0.f;
}
__global__ void k_zero_red(){ if (threadIdx.x < 2) g_red[threadIdx.x] = 0.0; }

__global__ void k_degree(const int* __restrict__ dst, const float* __restrict__ ea){
    int t = blockIdx.x*blockDim.x + threadIdx.x;
    if (t >= NE*8) return;
    int e = t >> 3, q = t & 7;
    int d = dst[e];
    float4 v = *(const float4*)(ea + (size_t)e*EDIM + q*4);
    float* base = g_loopea + (size_t)d*EDIM + q*4;
    atomicAdd(base+0, v.x); atomicAdd(base+1, v.y);
    atomicAdd(base+2, v.z); atomicAdd(base+3, v.w);
    if (q == 0) atomicAdd(&g_deg[d], 1.f);
}
__global__ void k_divloop(){
    int t = blockIdx.x*blockDim.x + threadIdx.x;
    if (t >= N_NODES*EDIM) return;
    float d = g_deg[t >> 5];
    g_loopea[t] = g_loopea[t] / fmaxf(d, 1.f);
}

// single-block scan over degrees (incl self loop) -> csr_ptr + cursor
__global__ void k_scan(){
    __shared__ int wsum[32];
    int tid = threadIdx.x, lane = tid & 31, w = tid >> 5;
    int carry = 0;
    if (tid == 0) g_csr_ptr[0] = 0;
    for (int base = 0; base < N_NODES; base += 1024) {
        int i = base + tid;
        int v = (i < N_NODES) ? ((int)g_deg[i] + 1) : 0;
        int x = v;
        #pragma unroll
        for (int off = 1; off < 32; off <<= 1) {
            int nb = __shfl_up_sync(0xffffffffu, x, off);
            if (lane >= off) x += nb;
        }
        if (lane == 31) wsum[w] = x;
        __syncthreads();
        if (w == 0) {
            int y = wsum[lane];
            #pragma unroll
            for (int off = 1; off < 32; off <<= 1) {
                int nb = __shfl_up_sync(0xffffffffu, y, off);
                if (lane >= off) y += nb;
            }
            wsum[lane] = y;
        }
        __syncthreads();
        int add  = (w > 0) ? wsum[w-1] : 0;
        int incl = carry + add + x;
        if (i < N_NODES) { g_csr_ptr[i+1] = incl; g_cursor[i] = incl - v; }
        carry += wsum[31];
        __syncthreads();
    }
}
__global__ void k_scatter(const int* __restrict__ src, const int* __restrict__ dst){
    int t = blockIdx.x*blockDim.x + threadIdx.x;
    if (t >= ETOT) return;
    int s, d;
    if (t < NE) { s = src[t]; d = dst[t]; } else { s = t - NE; d = s; }
    int pos = atomicAdd(&g_cursor[d], 1);
    g_csr_e[pos] = t;
    g_csr_s[pos] = s;
}

// concat wl|wr -> g_wcat [256][512]
__global__ void k_catw(const float* __restrict__ wl, const float* __restrict__ wr){
    int t = blockIdx.x*blockDim.x + threadIdx.x;   // 256*128 float4
    if (t >= HID*128) return;
    int k = t >> 7, q = t & 127;                   // q*4 = col
    int c = q * 4;
    float4 v = (c < HID) ? *(const float4*)(wl + (size_t)k*HID + c)
                         : *(const float4*)(wr + (size_t)k*HID + (c - HID));
    *(float4*)(g_wcat + (size_t)k*512 + c) = v;
}

// ---------------- fp32 SGEMM: C = act(A @ B + bias), BM=BN=128, BK=16 --------
__global__ __launch_bounds__(256) void sgemm(
    const float* __restrict__ A, const float* __restrict__ B,
    const float* __restrict__ bias, float* __restrict__ C,
    int M, int K, int Nn, int act)
{
    __shared__ float As[16][128];
    __shared__ float Bs[16][128];
    const int cRow = blockIdx.y * 128;
    const int cCol = blockIdx.x * 128;
    const int tid  = threadIdx.x;
    const int arow = tid >> 1;              // 0..127
    const int acol = (tid & 1) * 8;         // k base 0 or 8
    const int brow = tid >> 4;              // 0..15
    const int bcol = (tid & 15) * 8;        // 0..120
    const int tr = (tid >> 4) * 8;
    const int tc = (tid & 15) * 8;
    float acc[8][8];
    #pragma unroll
    for (int i = 0; i < 8; i++)
        #pragma unroll
        for (int j = 0; j < 8; j++) acc[i][j] = 0.f;

    for (int kt = 0; kt < K; kt += 16) {
        int gr = cRow + arow;
        float4 a0 = make_float4(0,0,0,0), a1 = a0;
        if (gr < M) {
            const float* Ab = A + (size_t)gr*K + kt + acol;
            a0 = *(const float4*)(Ab);
            a1 = *(const float4*)(Ab + 4);
        }
        As[acol+0][arow] = a0.x; As[acol+1][arow] = a0.y;
        As[acol+2][arow] = a0.z; As[acol+3][arow] = a0.w;
        As[acol+4][arow] = a1.x; As[acol+5][arow] = a1.y;
        As[acol+6][arow] = a1.z; As[acol+7][arow] = a1.w;
        {
            const float* Bb = B + (size_t)(kt + brow)*Nn + cCol + bcol;
            *(float4*)(&Bs[brow][bcol])   = *(const float4*)(Bb);
            *(float4*)(&Bs[brow][bcol+4]) = *(const float4*)(Bb + 4);
        }
        __syncthreads();
        #pragma unroll
        for (int k = 0; k < 16; k++) {
            float4 av0 = *(const float4*)&As[k][tr];
            float4 av1 = *(const float4*)&As[k][tr+4];
            float4 bv0 = *(const float4*)&Bs[k][tc];
            float4 bv1 = *(const float4*)&Bs[k][tc+4];
            float ra[8] = {av0.x,av0.y,av0.z,av0.w,av1.x,av1.y,av1.z,av1.w};
            float rb[8] = {bv0.x,bv0.y,bv0.z,bv0.w,bv1.x,bv1.y,bv1.z,bv1.w};
            #pragma unroll
            for (int i = 0; i < 8; i++)
                #pragma unroll
                for (int j = 0; j < 8; j++) acc[i][j] += ra[i]*rb[j];
        }
        __syncthreads();
    }
    #pragma unroll
    for (int i = 0; i < 8; i++) {
        int r = cRow + tr + i;
        if (r >= M) continue;
        #pragma unroll
        for (int j = 0; j < 8; j += 4) {
            int col = cCol + tc + j;
            float4 v = make_float4(acc[i][j], acc[i][j+1], acc[i][j+2], acc[i][j+3]);
            if (bias) {
                v.x += bias[col];   v.y += bias[col+1];
                v.z += bias[col+2]; v.w += bias[col+3];
            }
            if (act == 1) {
                v.x = fmaxf(v.x, 0.f); v.y = fmaxf(v.y, 0.f);
                v.z = fmaxf(v.z, 0.f); v.w = fmaxf(v.w, 0.f);
            }
            *(float4*)(C + (size_t)r*Nn + col) = v;
        }
    }
}

// ---------------- fused ep-GEMM + logits -------------------------------------
// Per block: 128 edges. ep = ea2 @ we computed in registers (two 128-col
// halves), epilogue gathers xl/xr, logits = sum_c lrelu(xl+xr+ep)*att[c].
__global__ __launch_bounds__(256) void k_eplogits(
    const int* __restrict__ src, const int* __restrict__ dst,
    const float* __restrict__ ea, const float* __restrict__ we,
    const float* __restrict__ attL)
{
    __shared__ float ea_s[EDIM][128];     // [k][edge]
    __shared__ float we_s[EDIM][128];     // [k][col] (per half)
    __shared__ int   s_src[128], s_dst[128];
    const int tid = threadIdx.x;
    const int e0  = blockIdx.x * 128;

    for (int i = tid; i < 128; i += 256) {
        int ge = e0 + i, s = 0, d = 0;
        if (ge < ETOT) {
            if (ge < NE) { s = src[ge]; d = dst[ge]; } else { s = ge - NE; d = s; }
        }
        s_src[i] = s; s_dst[i] = d;
    }
    for (int t = tid; t < 128*8; t += 256) {
        int i = t >> 3, q = t & 7;
        int ge = e0 + i;
        float4 v = make_float4(0,0,0,0);
        if (ge < ETOT) {
            const float* row = (ge < NE) ? (ea + (size_t)ge*EDIM)
                                         : (g_loopea + (size_t)(ge - NE)*EDIM);
            v = *(const float4*)(row + q*4);
        }
        ea_s[q*4+0][i] = v.x; ea_s[q*4+1][i] = v.y;
        ea_s[q*4+2][i] = v.z; ea_s[q*4+3][i] = v.w;
    }
    const int tr = (tid >> 4) * 8;      // edge base (8 edges)
    const int tc = (tid & 15) * 8;      // col base within half (8 cols)

    for (int half = 0; half < 2; half++) {
        __syncthreads();
        for (int t = tid; t < EDIM*32; t += 256) {    // 32 k-rows x 32 float4
            int k = t >> 5, q = t & 31;
            *(float4*)&we_s[k][q*4] =
                *(const float4*)(we + (size_t)k*HID + half*128 + q*4);
        }
        __syncthreads();

        float acc[8][8];
        #pragma unroll
        for (int i = 0; i < 8; i++)
            #pragma unroll
            for (int j = 0; j < 8; j++) acc[i][j] = 0.f;
        #pragma unroll
        for (int k = 0; k < EDIM; k++) {
            float4 av0 = *(const float4*)&ea_s[k][tr];
            float4 av1 = *(const float4*)&ea_s[k][tr+4];
            float4 bv0 = *(const float4*)&we_s[k][tc];
            float4 bv1 = *(const float4*)&we_s[k][tc+4];
            float ra[8] = {av0.x,av0.y,av0.z,av0.w,av1.x,av1.y,av1.z,av1.w};
            float rb[8] = {bv0.x,bv0.y,bv0.z,bv0.w,bv1.x,bv1.y,bv1.z,bv1.w};
            #pragma unroll
            for (int i = 0; i < 8; i++)
                #pragma unroll
                for (int j = 0; j < 8; j++) acc[i][j] += ra[i]*rb[j];
        }
        // epilogue: logits partials
        const int colg = half*128 + tc;            // global col base
        const int head = colg >> 6;
        float attv[8];
        {
            float4 w0 = *(const float4*)(attL + head*CDIM + (colg & 63));
            float4 w1 = *(const float4*)(attL + head*CDIM + (colg & 63) + 4);
            attv[0]=w0.x; attv[1]=w0.y; attv[2]=w0.z; attv[3]=w0.w;
            attv[4]=w1.x; attv[5]=w1.y; attv[6]=w1.z; attv[7]=w1.w;
        }
        float partial[8];
        #pragma unroll
        for (int i = 0; i < 8; i++) {
            int ge = e0 + tr + i;
            float p = 0.f;
            if (ge < ETOT) {
                int s = s_src[tr+i], d = s_dst[tr+i];
                const float* pl = g_xlr + (size_t)s*512 + colg;
                const float* pr = g_xlr + (size_t)d*512 + 256 + colg;
                float4 l0 = *(const float4*)(pl);
                float4 l1 = *(const float4*)(pl+4);
                float4 r0 = *(const float4*)(pr);
                float4 r1 = *(const float4*)(pr+4);
                float xs[8] = {l0.x+r0.x, l0.y+r0.y, l0.z+r0.z, l0.w+r0.w,
                               l1.x+r1.x, l1.y+r1.y, l1.z+r1.z, l1.w+r1.w};
                #pragma unroll
                for (int j = 0; j < 8; j++)
                    p += lrelu(acc[i][j] + xs[j]) * attv[j];
            }
            partial[i] = p;
        }
        #pragma unroll
        for (int i = 0; i < 8; i++) {
            float p = partial[i];
            p += __shfl_down_sync(0xffffffffu, p, 4, 8);
            p += __shfl_down_sync(0xffffffffu, p, 2, 8);
            p += __shfl_down_sync(0xffffffffu, p, 1, 8);
            partial[i] = p;
        }
        if ((tid & 7) == 0) {
            #pragma unroll
            for (int i = 0; i < 8; i++) {
                int ge = e0 + tr + i;
                if (ge < ETOT) g_logits[(size_t)ge*HEADS + head] = partial[i];
            }
        }
    }
}

// ---------------- node aggregation: softmax + weighted sum + post ------------
// warp per node; fused bias + ELU + residual + LN sum/sumsq reduction
__global__ __launch_bounds__(256) void k_nodeagg(const float* __restrict__ bconv){
    const int n    = (blockIdx.x*256 + threadIdx.x) >> 5;   // exact: 50000 warps
    const int lane = threadIdx.x & 31;
    const int p0 = g_csr_ptr[n], p1 = g_csr_ptr[n+1];
    // phase A: segment max per head
    float4 mx = make_float4(-1e30f,-1e30f,-1e30f,-1e30f);
    for (int idx = p0 + lane; idx < p1; idx += 32) {
        int e = g_csr_e[idx];
        float4 lg = *(const float4*)(g_logits + (size_t)e*HEADS);
        mx.x = fmaxf(mx.x, lg.x); mx.y = fmaxf(mx.y, lg.y);
        mx.z = fmaxf(mx.z, lg.z); mx.w = fmaxf(mx.w, lg.w);
    }
    #pragma unroll
    for (int off = 16; off; off >>= 1) {
        mx.x = fmaxf(mx.x, __shfl_xor_sync(0xffffffffu, mx.x, off));
        mx.y = fmaxf(mx.y, __shfl_xor_sync(0xffffffffu, mx.y, off));
        mx.z = fmaxf(mx.z, __shfl_xor_sync(0xffffffffu, mx.z, off));
        mx.w = fmaxf(mx.w, __shfl_xor_sync(0xffffffffu, mx.w, off));
    }
    // phase B: denom
    float4 sm = make_float4(0,0,0,0);
    for (int idx = p0 + lane; idx < p1; idx += 32) {
        int e = g_csr_e[idx];
        float4 lg = *(const float4*)(g_logits + (size_t)e*HEADS);
        sm.x += expf(lg.x - mx.x); sm.y += expf(lg.y - mx.y);
        sm.z += expf(lg.z - mx.z); sm.w += expf(lg.w - mx.w);
    }
    #pragma unroll
    for (int off = 16; off; off >>= 1) {
        sm.x += __shfl_xor_sync(0xffffffffu, sm.x, off);
        sm.y += __shfl_xor_sync(0xffffffffu, sm.y, off);
        sm.z += __shfl_xor_sync(0xffffffffu, sm.z, off);
        sm.w += __shfl_xor_sync(0xffffffffu, sm.w, off);
    }
    const int head = lane >> 3;
    const float mh = sel4(mx, head);
    const float ih = 1.f / (sel4(sm, head) + 1e-16f);
    // phase C: weighted aggregation (8 cols per lane)
    float acc[8];
    #pragma unroll
    for (int j = 0; j < 8; j++) acc[j] = 0.f;
    for (int idx = p0; idx < p1; idx++) {
        int e = g_csr_e[idx];
        int s = g_csr_s[idx];
        float4 lg = *(const float4*)(g_logits + (size_t)e*HEADS);
        float w = expf(sel4(lg, head) - mh) * ih;
        const float* px = g_xlr + (size_t)s*512 + lane*8;
        float4 x0 = *(const float4*)(px);
        float4 x1 = *(const float4*)(px+4);
        acc[0] += w*x0.x; acc[1] += w*x0.y; acc[2] += w*x0.z; acc[3] += w*x0.w;
        acc[4] += w*x1.x; acc[5] += w*x1.y; acc[6] += w*x1.z; acc[7] += w*x1.w;
    }
    // epilogue: bias + ELU + residual, store, LN reduce
    float* ph = g_h + (size_t)n*HID + lane*8;
    float4 h0 = *(const float4*)(ph);
    float4 h1 = *(const float4*)(ph+4);
    float4 b0 = *(const float4*)(bconv + lane*8);
    float4 b1 = *(const float4*)(bconv + lane*8 + 4);
    float hv[8] = {h0.x,h0.y,h0.z,h0.w,h1.x,h1.y,h1.z,h1.w};
    float bv[8] = {b0.x,b0.y,b0.z,b0.w,b1.x,b1.y,b1.z,b1.w};
    float s_ = 0.f, q_ = 0.f;
    float out8[8];
    #pragma unroll
    for (int j = 0; j < 8; j++) {
        float v  = acc[j] + bv[j];
        float el = v > 0.f ? v : (expf(v) - 1.f);
        float t  = hv[j] + el;
        out8[j] = t; s_ += t; q_ += t*t;
    }
    *(float4*)(ph)   = make_float4(out8[0],out8[1],out8[2],out8[3]);
    *(float4*)(ph+4) = make_float4(out8[4],out8[5],out8[6],out8[7]);
    #pragma unroll
    for (int off = 16; off; off >>= 1) {
        s_ += __shfl_down_sync(0xffffffffu, s_, off);
        q_ += __shfl_down_sync(0xffffffffu, q_, off);
    }
    __shared__ float ss[8], sq[8];
    int w = threadIdx.x >> 5;
    if (lane == 0) { ss[w] = s_; sq[w] = q_; }
    __syncthreads();
    if (threadIdx.x == 0) {
        float S = 0.f, Q = 0.f;
        #pragma unroll
        for (int i = 0; i < 8; i++) { S += ss[i]; Q += sq[i]; }
        atomicAdd(&g_red[0], (double)S);
        atomicAdd(&g_red[1], (double)Q);
    }
}

// ---------------- graph layer norm apply -------------------------------------
__global__ void k_norm(const float* __restrict__ lnw, const float* __restrict__ lnb){
    int idx = blockIdx.x*blockDim.x + threadIdx.x;
    if (idx >= TOT_H) return;
    int c = idx & (HID-1);
    double M  = (double)TOT_H;
    double mu = g_red[0] / M;
    double var = g_red[1] / M - mu*mu;
    if (var < 0.0) var = 0.0;
    float rs = (float)(1.0 / (sqrt(var) + 1e-5));
    g_h[idx] = (g_h[idx] - (float)mu) * rs * lnw[c] + lnb[c];
}

// ---------------- launcher ---------------------------------------------------
extern "C" void kernel_launch(void* const* d_in, const int* in_sizes, int n_in,
                              void* d_out, int out_size)
{
    const float* x     = (const float*)d_in[0];
    const int*   ei    = (const int*)  d_in[1];
    const float* ea    = (const float*)d_in[2];
    const float* w_in  = (const float*)d_in[3];
    const float* b_in  = (const float*)d_in[4];
    const float* wl    = (const float*)d_in[5];
    const float* wr    = (const float*)d_in[6];
    const float* we    = (const float*)d_in[7];
    const float* att   = (const float*)d_in[8];
    const float* bconv = (const float*)d_in[9];
    const float* lnw   = (const float*)d_in[10];
    const float* lnb   = (const float*)d_in[11];
    const float* wout  = (const float*)d_in[12];
    const float* bout  = (const float*)d_in[13];
    float* out = (float*)d_out;
    const int* srcA = ei;
    const int* dstA = ei + NE;

    float *p_h, *p_xlr, *p_loop, *p_deg, *p_wcat;
    cudaGetSymbolAddress((void**)&p_h,    g_h);
    cudaGetSymbolAddress((void**)&p_xlr,  g_xlr);
    cudaGetSymbolAddress((void**)&p_loop, g_loopea);
    cudaGetSymbolAddress((void**)&p_deg,  g_deg);
    cudaGetSymbolAddress((void**)&p_wcat, g_wcat);

    // self-loop edge attrs + CSR build
    k_zero_f<<<(unsigned)(((size_t)N_NODES*EDIM + 511)/512), 512>>>(p_loop, (size_t)N_NODES*EDIM);
    k_zero_f<<<(N_NODES + 511)/512, 512>>>(p_deg, (size_t)N_NODES);
    k_degree<<<(NE*8 + 255)/256, 256>>>(dstA, ea);
    k_divloop<<<(N_NODES*EDIM + 255)/256, 256>>>();
    k_scan<<<1, 1024>>>();
    k_scatter<<<(ETOT + 255)/256, 256>>>(srcA, dstA);

    dim3 gIn (HID/128, (N_NODES + 127)/128);
    dim3 gXlr(512/128, (N_NODES + 127)/128);
    sgemm<<<gIn, 256>>>(x, w_in, b_in, p_h, N_NODES, DIN, HID, 1);

    for (int l = 0; l < NLAYER; l++) {
        k_catw<<<(HID*128 + 255)/256, 256>>>(wl + (size_t)l*HID*HID,
                                             wr + (size_t)l*HID*HID);
        sgemm<<<gXlr, 256>>>(p_h, p_wcat, nullptr, p_xlr, N_NODES, HID, 512, 0);
        k_eplogits<<<(ETOT + 127)/128, 256>>>(srcA, dstA, ea,
                                              we + (size_t)l*EDIM*HID,
                                              att + (size_t)l*HEADS*CDIM);
        k_zero_red<<<1, 32>>>();
        k_nodeagg<<<N_NODES/8, 256>>>(bconv + (size_t)l*HID);
        k_norm<<<TOT_H/256, 256>>>(lnw + (size_t)l*HID, lnb + (size_t)l*HID);
    }
    sgemm<<<gIn, 256>>>(p_h, wout, bout, out, N_NODES, HID, HID, 0);
}